// round 15
// baseline (speedup 1.0000x reference)
#include <cuda_runtime.h>
#include <cuda_fp16.h>
#include <cstdint>

#define NCTA   145
#define NTH    512
#define HIDN   1200
#define HPAD   1216
#define BT     64
#define TS     512
#define ROUNDS 514
#define SM_XW  175104
#define SMEM_TOTAL 229120
#define WSTRIDE 24320          // uint2 per CTA weight pack (194560 B)

// ---------------- static device scratch ----------------
__device__ uint2 g_Wpk[(size_t)NCTA * WSTRIDE];
__device__ uint2 g_Wxp[50 * 9 * 2 * 32];
__device__ __align__(16) __half g_x16[TS * BT * 32];
__device__ __align__(16) __half g_h0h[2][BT * HPAD];
__device__ __align__(16) __half g_h1h[2][BT * HPAD];
__device__ float g_gi1[2][3600 * BT];
__device__ unsigned g_arrC[3 * 32];     // per-class arrive counters (128B apart)
__device__ unsigned g_epochC[3 * 32];   // per-class epochs (128B apart)

// ---------------- fused prep kernel (R12 layout) ----------------
__global__ void prep_all(const float* __restrict__ x,
                         const float* __restrict__ Wih0,
                         const float* __restrict__ Whh0,
                         const float* __restrict__ Wih1,
                         const float* __restrict__ Whh1) {
    int bid = blockIdx.x;
    int t = threadIdx.x;
    if (bid < 608) {
        int idx = bid * 256 + t;
        if (idx < 77824) ((unsigned*)g_h0h)[idx] = 0u;
        else             ((unsigned*)g_h1h)[idx - 77824] = 0u;
        if (idx < 3 * 32) { g_arrC[idx] = 0u; g_epochC[idx] = 0u; }
        return;
    }
    if (bid < 4704) {
        int idx = (bid - 608) * 256 + t;
        int i = idx & 31;
        int b = (idx >> 5) & 63;
        int tt = idx >> 11;
        float v = (i < 30) ? x[((size_t)b * TS + tt) * 30 + i] : 0.f;
        g_x16[idx] = __float2half_rn(v);
        return;
    }
    if (bid < 4817) {
        int idx = (bid - 4704) * 256 + t;
        if (idx >= 28800) return;
        int lane = idx & 31;
        int kt = (idx >> 5) & 1;
        int u = idx >> 6;
        int s = u % 9;
        int cta = u / 9;
        int row = (s / 3) * 1200 + cta * 24 + (s % 3) * 8 + (lane >> 2);
        int k0 = (lane & 3) * 8 + kt * 4;
        unsigned h[4];
#pragma unroll
        for (int c = 0; c < 4; ++c) {
            int k = k0 + c;
            float v = (k < 30) ? Wih0[(size_t)row * 30 + k] : 0.f;
            h[c] = (unsigned)__half_as_ushort(__float2half_rn(v));
        }
        uint2 o; o.x = h[0] | (h[1] << 16); o.y = h[2] | (h[3] << 16);
        g_Wxp[idx] = o;
        return;
    }
    {
        long idx = (long)(bid - 4817) * 256 + t;
        const long total = (long)NCTA * WSTRIDE;
        if (idx >= total) return;
        int cta = (int)(idx / WSTRIDE);
        int rem = (int)(idx % WSTRIDE);
        const bool ten = (cta >= 50 && cta < 95);
        const int blku2 = ten ? 320 : 288;
        if (!ten && rem >= 21888) return;
        int block = rem / blku2;
        int within = rem % blku2;
        int kc = block >> 1, e = block & 1;
        int slot, lane;
        if (!ten && within >= 256) { slot = 8; lane = within - 256; }
        else {
            int sp = within >> 6;
            lane = (within & 63) >> 1;
            slot = sp * 2 + (within & 1);
        }
        const float* W;
        int row0;
        if (cta < 50)       { W = Whh0; row0 = (slot / 3) * 1200 + cta * 24 + (slot % 3) * 8; }
        else if (cta < 95)  { W = Wih1; row0 = ((cta - 50) * 10 + slot) * 8; }
        else                { W = Whh1; row0 = (slot / 3) * 1200 + (cta - 95) * 24 + (slot % 3) * 8; }
        int row = row0 + (lane >> 2);
        int k0 = kc * 32 + (lane & 3) * 8 + e * 4;
        unsigned h[4];
#pragma unroll
        for (int c = 0; c < 4; ++c) {
            int k = k0 + c;
            float vv = (k < 1200) ? W[(size_t)row * 1200 + k] : 0.f;
            h[c] = (unsigned)__half_as_ushort(__float2half_rn(vv));
        }
        uint2 o; o.x = h[0] | (h[1] << 16); o.y = h[2] | (h[3] << 16);
        g_Wpk[(size_t)cta * WSTRIDE + rem] = o;
    }
}

// ---------------- device helpers ----------------
__device__ __forceinline__ void mma_16816(float c[4],
    unsigned a0, unsigned a1, unsigned a2, unsigned a3, unsigned b0, unsigned b1) {
    asm volatile(
        "mma.sync.aligned.m16n8k16.row.col.f32.f16.f16.f32 "
        "{%0,%1,%2,%3},{%4,%5,%6,%7},{%8,%9},{%0,%1,%2,%3};"
        : "+f"(c[0]), "+f"(c[1]), "+f"(c[2]), "+f"(c[3])
        : "r"(a0), "r"(a1), "r"(a2), "r"(a3), "r"(b0), "r"(b1));
}
__device__ __forceinline__ void cpa16(void* s, const void* g) {
    unsigned sa = (unsigned)__cvta_generic_to_shared(s);
    asm volatile("cp.async.cg.shared.global [%0],[%1],16;" :: "r"(sa), "l"(g));
}
__device__ __forceinline__ void cp_commit() { asm volatile("cp.async.commit_group;"); }
template <int N> __device__ __forceinline__ void cp_wait() {
    asm volatile("cp.async.wait_group %0;" :: "n"(N));
}
__device__ __forceinline__ float sigf(float x) {
    return __fdividef(1.f, 1.f + __expf(-x));
}
__device__ __forceinline__ float tanhf_fast(float x) {
    return __fdividef(2.f, 1.f + __expf(-2.f * x)) - 1.f;
}
__device__ __forceinline__ void waitE(const unsigned* p, unsigned tgt) {
    unsigned e;
    int slp = 8;
    while (true) {
        asm volatile("ld.global.cg.u32 %0,[%1];" : "=r"(e) : "l"(p));
        if (e >= tgt) break;
        __nanosleep(slp);
        if (slp < 64) slp += slp;
    }
}

__device__ __forceinline__ void ldA128(uint4 (&d)[2], const char* aBase,
                                       int rowA0, int tid4, int kc, int rstride) {
#pragma unroll
    for (int p = 0; p < 2; ++p) {
        const char* ptr = aBase + (size_t)(rowA0 + p * 8) * rstride
                          + kc * 64 + tid4 * 16;
        asm volatile("ld.global.cg.v4.u32 {%0,%1,%2,%3},[%4];"
                     : "=r"(d[p].x), "=r"(d[p].y), "=r"(d[p].z), "=r"(d[p].w)
                     : "l"(ptr));
    }
}

template<int NS>
__device__ __forceinline__ void slots_v(const char* wk, int lane,
                                        const uint4 (&cu)[2], bool hi,
                                        float (&acc)[NS][4]) {
    unsigned a0 = hi ? cu[0].z : cu[0].x;
    unsigned a1 = hi ? cu[1].z : cu[1].x;
    unsigned a2 = hi ? cu[0].w : cu[0].y;
    unsigned a3 = hi ? cu[1].w : cu[1].y;
#pragma unroll
    for (int sp = 0; sp < NS / 2; ++sp) {
        uint4 wp = *(const uint4*)(wk + sp * 512 + lane * 16);
        mma_16816(acc[sp * 2],     a0, a1, a2, a3, wp.x, wp.y);
        mma_16816(acc[sp * 2 + 1], a0, a1, a2, a3, wp.z, wp.w);
    }
    if (NS & 1) {
        uint2 w = *(const uint2*)(wk + (NS / 2) * 512 + lane * 8);
        mma_16816(acc[NS - 1], a0, a1, a2, a3, w.x, w.y);
    }
}

template<int NS>
__device__ __forceinline__ void run_kloopv(const char* aBase, const char* smB,
        int kc_lo, int kc_hi, int rowA0, int tid4, int lane, float (&acc)[NS][4]) {
    const int EB = (NS == 9) ? 2304 : 2560;
    const char* wk = smB + kc_lo * 2 * EB;
    uint4 cur[2], nxt[2];
    ldA128(cur, aBase, rowA0, tid4, kc_lo, HPAD * 2);
#pragma unroll
    for (int p = 0; p < 2; ++p) nxt[p] = cur[p];
#pragma unroll 1
    for (int kc = kc_lo; kc < kc_hi; ++kc) {
        if (kc + 1 < kc_hi) ldA128(nxt, aBase, rowA0, tid4, kc + 1, HPAD * 2);
        slots_v<NS>(wk,      lane, cur, false, acc);
        slots_v<NS>(wk + EB, lane, cur, true,  acc);
        wk += 2 * EB;
#pragma unroll
        for (int p = 0; p < 2; ++p) cur[p] = nxt[p];
    }
}

template<int NS>
__device__ __forceinline__ void writePB(__half* PBh, int grp, const float (&acc)[NS][4],
                                        int rowA0, int tid4) {
#pragma unroll
    for (int s = 0; s < NS; ++s)
#pragma unroll
        for (int p = 0; p < 2; ++p) {
            int b = rowA0 + p * 8;
            __half2 v = __floats2half2_rn(acc[s][p * 2], acc[s][p * 2 + 1]);
            *(__half2*)(PBh + (grp * NS + s) * 512 + b * 8 + tid4 * 2) = v;
        }
}
template<int NS>
__device__ __forceinline__ void addPB(__half* PBh, int grp, float (&acc)[NS][4],
                                      int rowA0, int tid4) {
#pragma unroll
    for (int s = 0; s < NS; ++s)
#pragma unroll
        for (int p = 0; p < 2; ++p) {
            int b = rowA0 + p * 8;
            __half2 u = *(__half2*)(PBh + (grp * NS + s) * 512 + b * 8 + tid4 * 2);
            acc[s][p * 2]     += __low2float(u);
            acc[s][p * 2 + 1] += __high2float(u);
        }
}

// ---------------- persistent kernel (512 threads, class-decoupled epochs) ----------------
__global__ void __launch_bounds__(NTH, 1) gru_main(
    const float* __restrict__ b_ih0, const float* __restrict__ b_hh0,
    const float* __restrict__ b_ih1, const float* __restrict__ b_hh1,
    float* __restrict__ out)
{
    extern __shared__ char sm[];
    const int cta  = blockIdx.x;
    const int tid  = threadIdx.x;
    const int wid  = tid >> 5;
    const int lane = tid & 31;
    const int mw   = wid >> 2;
    const int kw   = wid & 3;
    const int g    = lane >> 2;
    const int tid4 = lane & 3;
    const int cls  = (cta < 50) ? 0 : (cta < 95) ? 1 : 2;
    const int nbig = (cls == 1) ? 10 : 9;
    const unsigned clsN = (cls == 1) ? 45u : 50u;

    const int kc_lo = (kw == 0) ? 0 : (kw == 1) ? 9 : (kw == 2) ? 19 : 29;
    const int kc_hi = (kw == 0) ? 9 : (kw == 1) ? 19 : (kw == 2) ? 29 : 38;
    const int rowA0 = mw * 16 + g;

    const int PB_off = (cls == 0) ? 179712 : (cls == 1) ? 194560 : 175104;
    __half* PBh = (__half*)(sm + PB_off);
    const int pbsz = 2 * nbig * 512 * 2;
    float*  pre  = (float*)(sm + PB_off + pbsz);
    const int presz = ((cls == 0) ? 12 : 9) * 64 * 9 * 4;
    __half* hbuf = (__half*)((char*)pre + presz);

    // ---- load resident weights ----
    {
        const uint2* wsrc = g_Wpk + (size_t)cta * WSTRIDE;
        int n16 = (cls == 1) ? 12160 : 10944;
        for (int i = tid; i < n16; i += NTH)
            cpa16(sm + i * 16, wsrc + i * 2);
        if (cls == 0) {
            const uint2* xs = g_Wxp + cta * 576;
            for (int i = tid; i < 288; i += NTH)
                cpa16(sm + SM_XW + i * 16, xs + i * 2);
        }
        cp_commit();
        cp_wait<0>();
        __syncthreads();
    }

    // ---- combine-side setup ----
    const int jbase = (cls == 0) ? cta * 24 : (cls == 2) ? (cta - 95) * 24 : 0;
    float bias[3][4];
    float hprev[3];
    if (cls != 1) {
        const float* bi = (cls == 0) ? b_ih0 : b_ih1;
        const float* bh = (cls == 0) ? b_hh0 : b_hh1;
#pragma unroll
        for (int q = 0; q < 3; ++q) {
            int jg = jbase + ((q * NTH + tid) >> 6);
            bias[q][0] = __ldg(bi + jg) + __ldg(bh + jg);
            bias[q][1] = __ldg(bi + 1200 + jg) + __ldg(bh + 1200 + jg);
            bias[q][2] = __ldg(bi + 2400 + jg);
            bias[q][3] = __ldg(bh + 2400 + jg);
            hprev[q] = 0.f;
        }
    }

    for (int r = 0; r < ROUNDS; ++r) {
        // ---- own-class start wait (all class CTAs finished round r-1) ----
        if (r > 0) {
            if (tid == 0) { waitE(&g_epochC[cls * 32], (unsigned)r); __threadfence(); }
            __syncthreads();
        }

        const bool act = (cls == 0) ? (r < TS)
                        : (cls == 1) ? (r >= 1 && r <= TS)
                                     : (r >= 2);
        if (act) {
            if (cls == 1) {
                float acc[10][4];
#pragma unroll
                for (int s = 0; s < 10; ++s)
#pragma unroll
                    for (int c = 0; c < 4; ++c) acc[s][c] = 0.f;

                // RAW: needs h0[r-1] = L0 finished round r-1
                if (tid == 0) { waitE(&g_epochC[0], (unsigned)r); __threadfence(); }
                __syncthreads();

                const char* aBase = (const char*)g_h0h[(r + 1) & 1];
                run_kloopv<10>(aBase, sm, kc_lo, kc_hi, rowA0, tid4, lane, acc);

                if (kw == 1) writePB<10>(PBh, 0, acc, rowA0, tid4);
                if (kw == 3) writePB<10>(PBh, 1, acc, rowA0, tid4);
                __syncthreads();
                if (kw == 0) addPB<10>(PBh, 0, acc, rowA0, tid4);
                if (kw == 2) { addPB<10>(PBh, 1, acc, rowA0, tid4);
                               writePB<10>(PBh, 1, acc, rowA0, tid4); }
                // WAR: gi1[(r-1)&1] still being read by H1 round r-1
                __syncthreads();
                if (tid == 0) { waitE(&g_epochC[2 * 32], (unsigned)r); __threadfence(); }
                __syncthreads();
                if (kw == 0) {
                    addPB<10>(PBh, 1, acc, rowA0, tid4);
                    float* gw = g_gi1[(r - 1) & 1];
#pragma unroll
                    for (int s = 0; s < 10; ++s)
#pragma unroll
                        for (int p = 0; p < 2; ++p) {
                            int b = rowA0 + p * 8;
                            int gr = ((cta - 50) * 10 + s) * 8 + tid4 * 2;
                            __stcg(gw + (size_t)gr * BT + b, acc[s][p * 2]);
                            __stcg(gw + (size_t)(gr + 1) * BT + b, acc[s][p * 2 + 1]);
                        }
                }
            } else {
                float acc[9][4];
#pragma unroll
                for (int s = 0; s < 9; ++s)
#pragma unroll
                    for (int c = 0; c < 4; ++c) acc[s][c] = 0.f;

                const char* aBase = (cls == 2) ? (const char*)g_h1h[(r + 1) & 1]
                                               : (const char*)g_h0h[(r + 1) & 1];

                float accIN[3][4];
                if (cls == 0 && kw == 3) {
#pragma unroll
                    for (int s = 0; s < 3; ++s)
#pragma unroll
                        for (int c = 0; c < 4; ++c) accIN[s][c] = 0.f;
                    const char* xb = (const char*)g_x16 + (size_t)r * 4096;
                    uint4 xa[2];
                    ldA128(xa, xb, rowA0, tid4, 0, 64);
#pragma unroll
                    for (int s = 0; s < 9; ++s) {
                        uint2 w0 = *(const uint2*)(sm + SM_XW + (s * 2) * 256 + lane * 8);
                        uint2 w1 = *(const uint2*)(sm + SM_XW + (s * 2 + 1) * 256 + lane * 8);
                        float* tgt = (s < 6) ? acc[s] : accIN[s - 6];
                        mma_16816(tgt, xa[0].x, xa[1].x, xa[0].y, xa[1].y, w0.x, w0.y);
                        mma_16816(tgt, xa[0].z, xa[1].z, xa[0].w, xa[1].w, w1.x, w1.y);
                    }
                }

                run_kloopv<9>(aBase, sm, kc_lo, kc_hi, rowA0, tid4, lane, acc);

                float giPre[3][3];
                if (cls == 2) {
                    // RAW: gi1[r&1] written by I1 round r-1
                    if (tid == 0) { waitE(&g_epochC[32], (unsigned)r); __threadfence(); }
                    __syncthreads();
                    const float* gi = g_gi1[r & 1];
#pragma unroll
                    for (int q = 0; q < 3; ++q) {
                        int pi = q * NTH + tid;
                        int b = pi & 63, j = pi >> 6;
                        int jg = jbase + j;
                        giPre[q][0] = __ldcg(gi + (size_t)jg * BT + b);
                        giPre[q][1] = __ldcg(gi + (size_t)(1200 + jg) * BT + b);
                        giPre[q][2] = __ldcg(gi + (size_t)(2400 + jg) * BT + b);
                    }
                }

                if (kw == 1) writePB<9>(PBh, 0, acc, rowA0, tid4);
                if (kw == 3) {
                    writePB<9>(PBh, 1, acc, rowA0, tid4);
                    if (cls == 0) {
#pragma unroll
                        for (int s = 0; s < 3; ++s)
#pragma unroll
                            for (int p = 0; p < 2; ++p) {
                                int b = rowA0 + p * 8;
                                float* pp = pre + ((9 + s) * 64 + b) * 9 + tid4 * 2;
                                pp[0] = accIN[s][p * 2];
                                pp[1] = accIN[s][p * 2 + 1];
                            }
                    }
                }
                __syncthreads();
                if (kw == 0) addPB<9>(PBh, 0, acc, rowA0, tid4);
                if (kw == 2) { addPB<9>(PBh, 1, acc, rowA0, tid4);
                               writePB<9>(PBh, 1, acc, rowA0, tid4); }
                __syncthreads();
                if (kw == 0) {
                    addPB<9>(PBh, 1, acc, rowA0, tid4);
#pragma unroll
                    for (int s = 0; s < 9; ++s)
#pragma unroll
                        for (int p = 0; p < 2; ++p) {
                            int b = rowA0 + p * 8;
                            float* pp = pre + (s * 64 + b) * 9 + tid4 * 2;
                            pp[0] = acc[s][p * 2];
                            pp[1] = acc[s][p * 2 + 1];
                        }
                }
                __syncthreads();

                // ---- combine (512 threads, 3 elements each) ----
                if (cls == 0) {
#pragma unroll
                    for (int q = 0; q < 3; ++q) {
                        int pi = q * NTH + tid;
                        int b = pi & 63, j = pi >> 6;
                        int sub = j >> 3, cl = j & 7;
                        float pR  = pre[((sub) * 64 + b) * 9 + cl];
                        float pZ  = pre[((3 + sub) * 64 + b) * 9 + cl];
                        float pHN = pre[((6 + sub) * 64 + b) * 9 + cl];
                        float pIN = pre[((9 + sub) * 64 + b) * 9 + cl];
                        float vr = sigf(pR + bias[q][0]);
                        float vz = sigf(pZ + bias[q][1]);
                        float vn = tanhf_fast(pIN + bias[q][2] + vr * (pHN + bias[q][3]));
                        float h = vn + vz * (hprev[q] - vn);
                        hprev[q] = h;
                        hbuf[b * 26 + j] = __float2half_rn(h);
                        if (r == TS - 1) out[(size_t)b * HIDN + jbase + j] = h;
                    }
                } else {
#pragma unroll
                    for (int q = 0; q < 3; ++q) {
                        int pi = q * NTH + tid;
                        int b = pi & 63, j = pi >> 6;
                        int sub = j >> 3, cl = j & 7;
                        float pR  = pre[((sub) * 64 + b) * 9 + cl];
                        float pZ  = pre[((3 + sub) * 64 + b) * 9 + cl];
                        float pHN = pre[((6 + sub) * 64 + b) * 9 + cl];
                        float vr = sigf(giPre[q][0] + pR + bias[q][0]);
                        float vz = sigf(giPre[q][1] + pZ + bias[q][1]);
                        float vn = tanhf_fast(giPre[q][2] + bias[q][2] + vr * (pHN + bias[q][3]));
                        float h = vn + vz * (hprev[q] - vn);
                        hprev[q] = h;
                        hbuf[b * 26 + j] = __float2half_rn(h);
                        if (r == TS + 1) out[76800 + (size_t)b * HIDN + jbase + j] = h;
                    }
                }
                __syncthreads();
                // L0 WAR: h0h[r&1] still being read by I1 round r-1
                if (cls == 0) {
                    if (tid == 0) { waitE(&g_epochC[32], (unsigned)r); __threadfence(); }
                    __syncthreads();
                }
                {
                    __half* dstH = (cls == 0) ? g_h0h[r & 1] : g_h1h[r & 1];
                    const unsigned* hb32 = (const unsigned*)hbuf;
#pragma unroll
                    for (int k = 0; k < 2; ++k) {
                        int idx = tid + k * NTH;
                        if (idx < 768) {
                            int row = idx / 12, c = idx % 12;
                            unsigned v = hb32[row * 13 + c];
                            asm volatile("st.global.cg.u32 [%0], %1;"
                                         :: "l"(dstH + (size_t)row * HPAD + jbase + c * 2),
                                            "r"(v) : "memory");
                        }
                    }
                }
            }
        }

        // ---- class-local arrive ----
        __threadfence();
        __syncthreads();
        if (tid == 0) {
            unsigned a = atomicAdd(&g_arrC[cls * 32], 1u);
            if (a == clsN - 1) {
                g_arrC[cls * 32] = 0u;
                __threadfence();
                atomicExch(&g_epochC[cls * 32], (unsigned)(r + 1));
            }
        }
    }
}

// ---------------- launch ----------------
extern "C" void kernel_launch(void* const* d_in, const int* in_sizes, int n_in,
                              void* d_out, int out_size) {
    const float* x     = (const float*)d_in[0];
    const float* W_ih0 = (const float*)d_in[1];
    const float* W_hh0 = (const float*)d_in[2];
    const float* b_ih0 = (const float*)d_in[3];
    const float* b_hh0 = (const float*)d_in[4];
    const float* W_ih1 = (const float*)d_in[5];
    const float* W_hh1 = (const float*)d_in[6];
    const float* b_ih1 = (const float*)d_in[7];
    const float* b_hh1 = (const float*)d_in[8];
    float* out = (float*)d_out;

    cudaFuncSetAttribute(gru_main,
                         cudaFuncAttributeMaxDynamicSharedMemorySize, SMEM_TOTAL);

    prep_all<<<18592, 256>>>(x, W_ih0, W_hh0, W_ih1, W_hh1);
    gru_main<<<NCTA, NTH, SMEM_TOTAL>>>(b_ih0, b_hh0, b_ih1, b_hh1, out);
}

// round 16
// speedup vs baseline: 1.1036x; 1.1036x over previous
#include <cuda_runtime.h>
#include <cuda_fp16.h>
#include <cstdint>

#define NCTA   145
#define NTH    512
#define HIDN   1200
#define HPAD   1216
#define BT     64
#define TS     512
#define ROUNDS 514
#define SM_XW  175104
#define SMEM_TOTAL 229120
#define WSTRIDE 24320          // uint2 per CTA weight pack (194560 B)
#define NGRP   10

// ---------------- static device scratch ----------------
__device__ uint2 g_Wpk[(size_t)NCTA * WSTRIDE];
__device__ uint2 g_Wxp[50 * 9 * 2 * 32];
__device__ __align__(16) __half g_x16[TS * BT * 32];
__device__ __align__(16) __half g_h0h[2][BT * HPAD];
__device__ __align__(16) __half g_h1h[2][BT * HPAD];
__device__ float g_gi1[2][3600 * BT];
__device__ unsigned g_arrG[NGRP * 32];   // group arrival counters, 128B apart
__device__ unsigned g_arrR;              // root counter
__device__ unsigned g_epoch;

// ---------------- fused prep kernel (R12 layout) ----------------
__global__ void prep_all(const float* __restrict__ x,
                         const float* __restrict__ Wih0,
                         const float* __restrict__ Whh0,
                         const float* __restrict__ Wih1,
                         const float* __restrict__ Whh1) {
    int bid = blockIdx.x;
    int t = threadIdx.x;
    if (bid < 608) {
        int idx = bid * 256 + t;
        if (idx < 77824) ((unsigned*)g_h0h)[idx] = 0u;
        else             ((unsigned*)g_h1h)[idx - 77824] = 0u;
        if (idx < NGRP * 32) g_arrG[idx] = 0u;
        if (idx == 0) { g_arrR = 0u; g_epoch = 0u; }
        return;
    }
    if (bid < 4704) {
        int idx = (bid - 608) * 256 + t;
        int i = idx & 31;
        int b = (idx >> 5) & 63;
        int tt = idx >> 11;
        float v = (i < 30) ? x[((size_t)b * TS + tt) * 30 + i] : 0.f;
        g_x16[idx] = __float2half_rn(v);
        return;
    }
    if (bid < 4817) {
        int idx = (bid - 4704) * 256 + t;
        if (idx >= 28800) return;
        int lane = idx & 31;
        int kt = (idx >> 5) & 1;
        int u = idx >> 6;
        int s = u % 9;
        int cta = u / 9;
        int row = (s / 3) * 1200 + cta * 24 + (s % 3) * 8 + (lane >> 2);
        int k0 = (lane & 3) * 8 + kt * 4;
        unsigned h[4];
#pragma unroll
        for (int c = 0; c < 4; ++c) {
            int k = k0 + c;
            float v = (k < 30) ? Wih0[(size_t)row * 30 + k] : 0.f;
            h[c] = (unsigned)__half_as_ushort(__float2half_rn(v));
        }
        uint2 o; o.x = h[0] | (h[1] << 16); o.y = h[2] | (h[3] << 16);
        g_Wxp[idx] = o;
        return;
    }
    {
        long idx = (long)(bid - 4817) * 256 + t;
        const long total = (long)NCTA * WSTRIDE;
        if (idx >= total) return;
        int cta = (int)(idx / WSTRIDE);
        int rem = (int)(idx % WSTRIDE);
        const bool ten = (cta >= 50 && cta < 95);
        const int blku2 = ten ? 320 : 288;
        if (!ten && rem >= 21888) return;
        int block = rem / blku2;
        int within = rem % blku2;
        int kc = block >> 1, e = block & 1;
        int slot, lane;
        if (!ten && within >= 256) { slot = 8; lane = within - 256; }
        else {
            int sp = within >> 6;
            lane = (within & 63) >> 1;
            slot = sp * 2 + (within & 1);
        }
        const float* W;
        int row0;
        if (cta < 50)       { W = Whh0; row0 = (slot / 3) * 1200 + cta * 24 + (slot % 3) * 8; }
        else if (cta < 95)  { W = Wih1; row0 = ((cta - 50) * 10 + slot) * 8; }
        else                { W = Whh1; row0 = (slot / 3) * 1200 + (cta - 95) * 24 + (slot % 3) * 8; }
        int row = row0 + (lane >> 2);
        int k0 = kc * 32 + (lane & 3) * 8 + e * 4;
        unsigned h[4];
#pragma unroll
        for (int c = 0; c < 4; ++c) {
            int k = k0 + c;
            float vv = (k < 1200) ? W[(size_t)row * 1200 + k] : 0.f;
            h[c] = (unsigned)__half_as_ushort(__float2half_rn(vv));
        }
        uint2 o; o.x = h[0] | (h[1] << 16); o.y = h[2] | (h[3] << 16);
        g_Wpk[(size_t)cta * WSTRIDE + rem] = o;
    }
}

// ---------------- device helpers ----------------
__device__ __forceinline__ void mma_16816(float c[4],
    unsigned a0, unsigned a1, unsigned a2, unsigned a3, unsigned b0, unsigned b1) {
    asm volatile(
        "mma.sync.aligned.m16n8k16.row.col.f32.f16.f16.f32 "
        "{%0,%1,%2,%3},{%4,%5,%6,%7},{%8,%9},{%0,%1,%2,%3};"
        : "+f"(c[0]), "+f"(c[1]), "+f"(c[2]), "+f"(c[3])
        : "r"(a0), "r"(a1), "r"(a2), "r"(a3), "r"(b0), "r"(b1));
}
__device__ __forceinline__ void cpa16(void* s, const void* g) {
    unsigned sa = (unsigned)__cvta_generic_to_shared(s);
    asm volatile("cp.async.cg.shared.global [%0],[%1],16;" :: "r"(sa), "l"(g));
}
__device__ __forceinline__ void cp_commit() { asm volatile("cp.async.commit_group;"); }
template <int N> __device__ __forceinline__ void cp_wait() {
    asm volatile("cp.async.wait_group %0;" :: "n"(N));
}
__device__ __forceinline__ float sigf(float x) {
    return __fdividef(1.f, 1.f + __expf(-x));
}
__device__ __forceinline__ float tanhf_fast(float x) {
    return __fdividef(2.f, 1.f + __expf(-2.f * x)) - 1.f;
}

__device__ __forceinline__ void ldA128(uint4 (&d)[2], const char* aBase,
                                       int rowA0, int tid4, int kc, int rstride) {
#pragma unroll
    for (int p = 0; p < 2; ++p) {
        const char* ptr = aBase + (size_t)(rowA0 + p * 8) * rstride
                          + kc * 64 + tid4 * 16;
        asm volatile("ld.global.cg.v4.u32 {%0,%1,%2,%3},[%4];"
                     : "=r"(d[p].x), "=r"(d[p].y), "=r"(d[p].z), "=r"(d[p].w)
                     : "l"(ptr));
    }
}

template<int NS>
__device__ __forceinline__ void slots_v(const char* wk, int lane,
                                        const uint4 (&cu)[2], bool hi,
                                        float (&acc)[NS][4]) {
    unsigned a0 = hi ? cu[0].z : cu[0].x;
    unsigned a1 = hi ? cu[1].z : cu[1].x;
    unsigned a2 = hi ? cu[0].w : cu[0].y;
    unsigned a3 = hi ? cu[1].w : cu[1].y;
#pragma unroll
    for (int sp = 0; sp < NS / 2; ++sp) {
        uint4 wp = *(const uint4*)(wk + sp * 512 + lane * 16);
        mma_16816(acc[sp * 2],     a0, a1, a2, a3, wp.x, wp.y);
        mma_16816(acc[sp * 2 + 1], a0, a1, a2, a3, wp.z, wp.w);
    }
    if (NS & 1) {
        uint2 w = *(const uint2*)(wk + (NS / 2) * 512 + lane * 8);
        mma_16816(acc[NS - 1], a0, a1, a2, a3, w.x, w.y);
    }
}

template<int NS>
__device__ __forceinline__ void run_kloopv(const char* aBase, const char* smB,
        int kc_lo, int kc_hi, int rowA0, int tid4, int lane, float (&acc)[NS][4]) {
    const int EB = (NS == 9) ? 2304 : 2560;
    const char* wk = smB + kc_lo * 2 * EB;
    uint4 cur[2], nxt[2];
    ldA128(cur, aBase, rowA0, tid4, kc_lo, HPAD * 2);
#pragma unroll
    for (int p = 0; p < 2; ++p) nxt[p] = cur[p];
#pragma unroll 1
    for (int kc = kc_lo; kc < kc_hi; ++kc) {
        if (kc + 1 < kc_hi) ldA128(nxt, aBase, rowA0, tid4, kc + 1, HPAD * 2);
        slots_v<NS>(wk,      lane, cur, false, acc);
        slots_v<NS>(wk + EB, lane, cur, true,  acc);
        wk += 2 * EB;
#pragma unroll
        for (int p = 0; p < 2; ++p) cur[p] = nxt[p];
    }
}

template<int NS>
__device__ __forceinline__ void writePB(__half* PBh, int grp, const float (&acc)[NS][4],
                                        int rowA0, int tid4) {
#pragma unroll
    for (int s = 0; s < NS; ++s)
#pragma unroll
        for (int p = 0; p < 2; ++p) {
            int b = rowA0 + p * 8;
            __half2 v = __floats2half2_rn(acc[s][p * 2], acc[s][p * 2 + 1]);
            *(__half2*)(PBh + (grp * NS + s) * 512 + b * 8 + tid4 * 2) = v;
        }
}
template<int NS>
__device__ __forceinline__ void addPB(__half* PBh, int grp, float (&acc)[NS][4],
                                      int rowA0, int tid4) {
#pragma unroll
    for (int s = 0; s < NS; ++s)
#pragma unroll
        for (int p = 0; p < 2; ++p) {
            int b = rowA0 + p * 8;
            __half2 u = *(__half2*)(PBh + (grp * NS + s) * 512 + b * 8 + tid4 * 2);
            acc[s][p * 2]     += __low2float(u);
            acc[s][p * 2 + 1] += __high2float(u);
        }
}

// ---------------- persistent kernel (512 threads) ----------------
__global__ void __launch_bounds__(NTH, 1) gru_main(
    const float* __restrict__ b_ih0, const float* __restrict__ b_hh0,
    const float* __restrict__ b_ih1, const float* __restrict__ b_hh1,
    float* __restrict__ out)
{
    extern __shared__ char sm[];
    const int cta  = blockIdx.x;
    const int tid  = threadIdx.x;
    const int wid  = tid >> 5;
    const int lane = tid & 31;
    const int mw   = wid >> 2;
    const int kw   = wid & 3;
    const int g    = lane >> 2;
    const int tid4 = lane & 3;
    const int cls  = (cta < 50) ? 0 : (cta < 95) ? 1 : 2;
    const int nbig = (cls == 1) ? 10 : 9;

    const int grp   = cta / 15;                          // 0..9
    const unsigned grpN = (grp == 9) ? 10u : 15u;        // 9*15+10 = 145

    const int kc_lo = (kw == 0) ? 0 : (kw == 1) ? 9 : (kw == 2) ? 19 : 29;
    const int kc_hi = (kw == 0) ? 9 : (kw == 1) ? 19 : (kw == 2) ? 29 : 38;
    const int rowA0 = mw * 16 + g;

    const int PB_off = (cls == 0) ? 179712 : (cls == 1) ? 194560 : 175104;
    __half* PBh = (__half*)(sm + PB_off);
    const int pbsz = 2 * nbig * 512 * 2;
    float*  pre  = (float*)(sm + PB_off + pbsz);
    const int presz = ((cls == 0) ? 12 : 9) * 64 * 9 * 4;
    __half* hbuf = (__half*)((char*)pre + presz);

    // ---- load resident weights ----
    {
        const uint2* wsrc = g_Wpk + (size_t)cta * WSTRIDE;
        int n16 = (cls == 1) ? 12160 : 10944;
        for (int i = tid; i < n16; i += NTH)
            cpa16(sm + i * 16, wsrc + i * 2);
        if (cls == 0) {
            const uint2* xs = g_Wxp + cta * 576;
            for (int i = tid; i < 288; i += NTH)
                cpa16(sm + SM_XW + i * 16, xs + i * 2);
        }
        cp_commit();
        cp_wait<0>();
        __syncthreads();
    }

    // ---- combine-side setup ----
    const int jbase = (cls == 0) ? cta * 24 : (cls == 2) ? (cta - 95) * 24 : 0;
    float bias[3][4];
    float hprev[3];
    if (cls != 1) {
        const float* bi = (cls == 0) ? b_ih0 : b_ih1;
        const float* bh = (cls == 0) ? b_hh0 : b_hh1;
#pragma unroll
        for (int q = 0; q < 3; ++q) {
            int jg = jbase + ((q * NTH + tid) >> 6);
            bias[q][0] = __ldg(bi + jg) + __ldg(bh + jg);
            bias[q][1] = __ldg(bi + 1200 + jg) + __ldg(bh + 1200 + jg);
            bias[q][2] = __ldg(bi + 2400 + jg);
            bias[q][3] = __ldg(bh + 2400 + jg);
            hprev[q] = 0.f;
        }
    }

    for (int r = 0; r < ROUNDS; ++r) {
        const bool act = (cls == 0) ? (r < TS)
                        : (cls == 1) ? (r >= 1 && r <= TS)
                                     : (r >= 2);
        if (act) {
            if (cls == 1) {
                float acc[10][4];
#pragma unroll
                for (int s = 0; s < 10; ++s)
#pragma unroll
                    for (int c = 0; c < 4; ++c) acc[s][c] = 0.f;

                const char* aBase = (const char*)g_h0h[(r + 1) & 1];
                run_kloopv<10>(aBase, sm, kc_lo, kc_hi, rowA0, tid4, lane, acc);

                if (kw == 1) writePB<10>(PBh, 0, acc, rowA0, tid4);
                if (kw == 3) writePB<10>(PBh, 1, acc, rowA0, tid4);
                __syncthreads();
                if (kw == 0) addPB<10>(PBh, 0, acc, rowA0, tid4);
                if (kw == 2) { addPB<10>(PBh, 1, acc, rowA0, tid4);
                               writePB<10>(PBh, 1, acc, rowA0, tid4); }
                __syncthreads();
                if (kw == 0) {
                    addPB<10>(PBh, 1, acc, rowA0, tid4);
                    float* gw = g_gi1[(r - 1) & 1];
#pragma unroll
                    for (int s = 0; s < 10; ++s)
#pragma unroll
                        for (int p = 0; p < 2; ++p) {
                            int b = rowA0 + p * 8;
                            int gr = ((cta - 50) * 10 + s) * 8 + tid4 * 2;
                            __stcg(gw + (size_t)gr * BT + b, acc[s][p * 2]);
                            __stcg(gw + (size_t)(gr + 1) * BT + b, acc[s][p * 2 + 1]);
                        }
                }
            } else {
                float acc[9][4];
#pragma unroll
                for (int s = 0; s < 9; ++s)
#pragma unroll
                    for (int c = 0; c < 4; ++c) acc[s][c] = 0.f;

                const char* aBase = (cls == 2) ? (const char*)g_h1h[(r + 1) & 1]
                                               : (const char*)g_h0h[(r + 1) & 1];

                float accIN[3][4];
                if (cls == 0 && kw == 3) {
#pragma unroll
                    for (int s = 0; s < 3; ++s)
#pragma unroll
                        for (int c = 0; c < 4; ++c) accIN[s][c] = 0.f;
                    const char* xb = (const char*)g_x16 + (size_t)r * 4096;
                    uint4 xa[2];
                    ldA128(xa, xb, rowA0, tid4, 0, 64);
#pragma unroll
                    for (int s = 0; s < 9; ++s) {
                        uint2 w0 = *(const uint2*)(sm + SM_XW + (s * 2) * 256 + lane * 8);
                        uint2 w1 = *(const uint2*)(sm + SM_XW + (s * 2 + 1) * 256 + lane * 8);
                        float* tgt = (s < 6) ? acc[s] : accIN[s - 6];
                        mma_16816(tgt, xa[0].x, xa[1].x, xa[0].y, xa[1].y, w0.x, w0.y);
                        mma_16816(tgt, xa[0].z, xa[1].z, xa[0].w, xa[1].w, w1.x, w1.y);
                    }
                }

                run_kloopv<9>(aBase, sm, kc_lo, kc_hi, rowA0, tid4, lane, acc);

                float giPre[3][3];
                if (cls == 2) {
                    const float* gi = g_gi1[r & 1];
#pragma unroll
                    for (int q = 0; q < 3; ++q) {
                        int pi = q * NTH + tid;
                        int b = pi & 63, j = pi >> 6;
                        int jg = jbase + j;
                        giPre[q][0] = __ldcg(gi + (size_t)jg * BT + b);
                        giPre[q][1] = __ldcg(gi + (size_t)(1200 + jg) * BT + b);
                        giPre[q][2] = __ldcg(gi + (size_t)(2400 + jg) * BT + b);
                    }
                }

                if (kw == 1) writePB<9>(PBh, 0, acc, rowA0, tid4);
                if (kw == 3) {
                    writePB<9>(PBh, 1, acc, rowA0, tid4);
                    if (cls == 0) {
#pragma unroll
                        for (int s = 0; s < 3; ++s)
#pragma unroll
                            for (int p = 0; p < 2; ++p) {
                                int b = rowA0 + p * 8;
                                float* pp = pre + ((9 + s) * 64 + b) * 9 + tid4 * 2;
                                pp[0] = accIN[s][p * 2];
                                pp[1] = accIN[s][p * 2 + 1];
                            }
                    }
                }
                __syncthreads();
                if (kw == 0) addPB<9>(PBh, 0, acc, rowA0, tid4);
                if (kw == 2) { addPB<9>(PBh, 1, acc, rowA0, tid4);
                               writePB<9>(PBh, 1, acc, rowA0, tid4); }
                __syncthreads();
                if (kw == 0) {
                    addPB<9>(PBh, 1, acc, rowA0, tid4);
#pragma unroll
                    for (int s = 0; s < 9; ++s)
#pragma unroll
                        for (int p = 0; p < 2; ++p) {
                            int b = rowA0 + p * 8;
                            float* pp = pre + (s * 64 + b) * 9 + tid4 * 2;
                            pp[0] = acc[s][p * 2];
                            pp[1] = acc[s][p * 2 + 1];
                        }
                }
                __syncthreads();

                // ---- combine (512 threads, 3 elements each) ----
                if (cls == 0) {
#pragma unroll
                    for (int q = 0; q < 3; ++q) {
                        int pi = q * NTH + tid;
                        int b = pi & 63, j = pi >> 6;
                        int sub = j >> 3, cl = j & 7;
                        float pR  = pre[((sub) * 64 + b) * 9 + cl];
                        float pZ  = pre[((3 + sub) * 64 + b) * 9 + cl];
                        float pHN = pre[((6 + sub) * 64 + b) * 9 + cl];
                        float pIN = pre[((9 + sub) * 64 + b) * 9 + cl];
                        float vr = sigf(pR + bias[q][0]);
                        float vz = sigf(pZ + bias[q][1]);
                        float vn = tanhf_fast(pIN + bias[q][2] + vr * (pHN + bias[q][3]));
                        float h = vn + vz * (hprev[q] - vn);
                        hprev[q] = h;
                        hbuf[b * 26 + j] = __float2half_rn(h);
                        if (r == TS - 1) out[(size_t)b * HIDN + jbase + j] = h;
                    }
                } else {
#pragma unroll
                    for (int q = 0; q < 3; ++q) {
                        int pi = q * NTH + tid;
                        int b = pi & 63, j = pi >> 6;
                        int sub = j >> 3, cl = j & 7;
                        float pR  = pre[((sub) * 64 + b) * 9 + cl];
                        float pZ  = pre[((3 + sub) * 64 + b) * 9 + cl];
                        float pHN = pre[((6 + sub) * 64 + b) * 9 + cl];
                        float vr = sigf(giPre[q][0] + pR + bias[q][0]);
                        float vz = sigf(giPre[q][1] + pZ + bias[q][1]);
                        float vn = tanhf_fast(giPre[q][2] + bias[q][2] + vr * (pHN + bias[q][3]));
                        float h = vn + vz * (hprev[q] - vn);
                        hprev[q] = h;
                        hbuf[b * 26 + j] = __float2half_rn(h);
                        if (r == TS + 1) out[76800 + (size_t)b * HIDN + jbase + j] = h;
                    }
                }
                __syncthreads();
                {
                    __half* dstH = (cls == 0) ? g_h0h[r & 1] : g_h1h[r & 1];
                    const unsigned* hb32 = (const unsigned*)hbuf;
#pragma unroll
                    for (int k = 0; k < 2; ++k) {
                        int idx = tid + k * NTH;
                        if (idx < 768) {
                            int row = idx / 12, c = idx % 12;
                            unsigned v = hb32[row * 13 + c];
                            asm volatile("st.global.cg.u32 [%0], %1;"
                                         :: "l"(dstH + (size_t)row * HPAD + jbase + c * 2),
                                            "r"(v) : "memory");
                        }
                    }
                }
            }
        }

        // ---- grid barrier: tid0 fence + 2-level grouped arrival ----
        __syncthreads();
        if (tid == 0) {
            __threadfence();   // release (cumulative over CTA via bar.sync)
            unsigned a = atomicAdd(&g_arrG[grp * 32], 1u);
            if (a == grpN - 1) {
                g_arrG[grp * 32] = 0u;
                unsigned rr = atomicAdd(&g_arrR, 1u);
                if (rr == NGRP - 1) {
                    g_arrR = 0u;
                    __threadfence();
                    atomicExch(&g_epoch, (unsigned)(r + 1));
                }
            }
            unsigned e;
            int slp = 8;
            while (true) {
                asm volatile("ld.global.cg.u32 %0,[%1];" : "=r"(e) : "l"(&g_epoch));
                if (e >= (unsigned)(r + 1)) break;
                __nanosleep(slp);
                if (slp < 64) slp += slp;
            }
            __threadfence();   // acquire
        }
        __syncthreads();
    }
}

// ---------------- launch ----------------
extern "C" void kernel_launch(void* const* d_in, const int* in_sizes, int n_in,
                              void* d_out, int out_size) {
    const float* x     = (const float*)d_in[0];
    const float* W_ih0 = (const float*)d_in[1];
    const float* W_hh0 = (const float*)d_in[2];
    const float* b_ih0 = (const float*)d_in[3];
    const float* b_hh0 = (const float*)d_in[4];
    const float* W_ih1 = (const float*)d_in[5];
    const float* W_hh1 = (const float*)d_in[6];
    const float* b_ih1 = (const float*)d_in[7];
    const float* b_hh1 = (const float*)d_in[8];
    float* out = (float*)d_out;

    cudaFuncSetAttribute(gru_main,
                         cudaFuncAttributeMaxDynamicSharedMemorySize, SMEM_TOTAL);

    prep_all<<<18592, 256>>>(x, W_ih0, W_hh0, W_ih1, W_hh1);
    gru_main<<<NCTA, NTH, SMEM_TOTAL>>>(b_ih0, b_hh0, b_ih1, b_hh1, out);
}

// round 17
// speedup vs baseline: 1.1781x; 1.0676x over previous
#include <cuda_runtime.h>
#include <cuda_fp16.h>
#include <cstdint>

#define NCTA   145
#define NTH    512
#define HIDN   1200
#define HPAD   1216
#define BT     64
#define TS     512
#define ROUNDS 514
#define SM_XW  175104
#define SMEM_TOTAL 229120
#define WSTRIDE 24320          // uint2 per CTA weight pack (194560 B)

// ---------------- static device scratch ----------------
__device__ uint2 g_Wpk[(size_t)NCTA * WSTRIDE];
__device__ uint2 g_Wxp[50 * 9 * 2 * 32];
__device__ __align__(16) __half g_x16[TS * BT * 32];
__device__ __align__(16) __half g_h0h[2][BT * HPAD];
__device__ __align__(16) __half g_h1h[2][BT * HPAD];
__device__ float g_gi1[2][3600 * BT];
__device__ unsigned g_arr;
__device__ unsigned g_epoch;

// ---------------- fused prep kernel (R12 layout) ----------------
__global__ void prep_all(const float* __restrict__ x,
                         const float* __restrict__ Wih0,
                         const float* __restrict__ Whh0,
                         const float* __restrict__ Wih1,
                         const float* __restrict__ Whh1) {
    int bid = blockIdx.x;
    int t = threadIdx.x;
    if (bid < 608) {
        int idx = bid * 256 + t;
        if (idx < 77824) ((unsigned*)g_h0h)[idx] = 0u;
        else             ((unsigned*)g_h1h)[idx - 77824] = 0u;
        if (idx == 0) { g_arr = 0u; g_epoch = 0u; }
        return;
    }
    if (bid < 4704) {
        int idx = (bid - 608) * 256 + t;
        int i = idx & 31;
        int b = (idx >> 5) & 63;
        int tt = idx >> 11;
        float v = (i < 30) ? x[((size_t)b * TS + tt) * 30 + i] : 0.f;
        g_x16[idx] = __float2half_rn(v);
        return;
    }
    if (bid < 4817) {
        int idx = (bid - 4704) * 256 + t;
        if (idx >= 28800) return;
        int lane = idx & 31;
        int kt = (idx >> 5) & 1;
        int u = idx >> 6;
        int s = u % 9;
        int cta = u / 9;
        int row = (s / 3) * 1200 + cta * 24 + (s % 3) * 8 + (lane >> 2);
        int k0 = (lane & 3) * 8 + kt * 4;
        unsigned h[4];
#pragma unroll
        for (int c = 0; c < 4; ++c) {
            int k = k0 + c;
            float v = (k < 30) ? Wih0[(size_t)row * 30 + k] : 0.f;
            h[c] = (unsigned)__half_as_ushort(__float2half_rn(v));
        }
        uint2 o; o.x = h[0] | (h[1] << 16); o.y = h[2] | (h[3] << 16);
        g_Wxp[idx] = o;
        return;
    }
    {
        long idx = (long)(bid - 4817) * 256 + t;
        const long total = (long)NCTA * WSTRIDE;
        if (idx >= total) return;
        int cta = (int)(idx / WSTRIDE);
        int rem = (int)(idx % WSTRIDE);
        const bool ten = (cta >= 50 && cta < 95);
        const int blku2 = ten ? 320 : 288;
        if (!ten && rem >= 21888) return;
        int block = rem / blku2;
        int within = rem % blku2;
        int kc = block >> 1, e = block & 1;
        int slot, lane;
        if (!ten && within >= 256) { slot = 8; lane = within - 256; }
        else {
            int sp = within >> 6;
            lane = (within & 63) >> 1;
            slot = sp * 2 + (within & 1);
        }
        const float* W;
        int row0;
        if (cta < 50)       { W = Whh0; row0 = (slot / 3) * 1200 + cta * 24 + (slot % 3) * 8; }
        else if (cta < 95)  { W = Wih1; row0 = ((cta - 50) * 10 + slot) * 8; }
        else                { W = Whh1; row0 = (slot / 3) * 1200 + (cta - 95) * 24 + (slot % 3) * 8; }
        int row = row0 + (lane >> 2);
        int k0 = kc * 32 + (lane & 3) * 8 + e * 4;
        unsigned h[4];
#pragma unroll
        for (int c = 0; c < 4; ++c) {
            int k = k0 + c;
            float vv = (k < 1200) ? W[(size_t)row * 1200 + k] : 0.f;
            h[c] = (unsigned)__half_as_ushort(__float2half_rn(vv));
        }
        uint2 o; o.x = h[0] | (h[1] << 16); o.y = h[2] | (h[3] << 16);
        g_Wpk[(size_t)cta * WSTRIDE + rem] = o;
    }
}

// ---------------- device helpers ----------------
__device__ __forceinline__ void mma_16816(float c[4],
    unsigned a0, unsigned a1, unsigned a2, unsigned a3, unsigned b0, unsigned b1) {
    asm volatile(
        "mma.sync.aligned.m16n8k16.row.col.f32.f16.f16.f32 "
        "{%0,%1,%2,%3},{%4,%5,%6,%7},{%8,%9},{%0,%1,%2,%3};"
        : "+f"(c[0]), "+f"(c[1]), "+f"(c[2]), "+f"(c[3])
        : "r"(a0), "r"(a1), "r"(a2), "r"(a3), "r"(b0), "r"(b1));
}
__device__ __forceinline__ void cpa16(void* s, const void* g) {
    unsigned sa = (unsigned)__cvta_generic_to_shared(s);
    asm volatile("cp.async.cg.shared.global [%0],[%1],16;" :: "r"(sa), "l"(g));
}
__device__ __forceinline__ void cp_commit() { asm volatile("cp.async.commit_group;"); }
template <int N> __device__ __forceinline__ void cp_wait() {
    asm volatile("cp.async.wait_group %0;" :: "n"(N));
}
__device__ __forceinline__ float sigf(float x) {
    return __fdividef(1.f, 1.f + __expf(-x));
}
__device__ __forceinline__ float tanhf_fast(float x) {
    return __fdividef(2.f, 1.f + __expf(-2.f * x)) - 1.f;
}

__device__ __forceinline__ void ldA128(uint4 (&d)[2], const char* aBase,
                                       int rowA0, int tid4, int kc, int rstride) {
#pragma unroll
    for (int p = 0; p < 2; ++p) {
        const char* ptr = aBase + (size_t)(rowA0 + p * 8) * rstride
                          + kc * 64 + tid4 * 16;
        asm volatile("ld.global.cg.v4.u32 {%0,%1,%2,%3},[%4];"
                     : "=r"(d[p].x), "=r"(d[p].y), "=r"(d[p].z), "=r"(d[p].w)
                     : "l"(ptr));
    }
}

template<int NS>
__device__ __forceinline__ void slots_v(const char* wk, int lane,
                                        const uint4 (&cu)[2], bool hi,
                                        float (&acc)[NS][4]) {
    unsigned a0 = hi ? cu[0].z : cu[0].x;
    unsigned a1 = hi ? cu[1].z : cu[1].x;
    unsigned a2 = hi ? cu[0].w : cu[0].y;
    unsigned a3 = hi ? cu[1].w : cu[1].y;
#pragma unroll
    for (int sp = 0; sp < NS / 2; ++sp) {
        uint4 wp = *(const uint4*)(wk + sp * 512 + lane * 16);
        mma_16816(acc[sp * 2],     a0, a1, a2, a3, wp.x, wp.y);
        mma_16816(acc[sp * 2 + 1], a0, a1, a2, a3, wp.z, wp.w);
    }
    if (NS & 1) {
        uint2 w = *(const uint2*)(wk + (NS / 2) * 512 + lane * 8);
        mma_16816(acc[NS - 1], a0, a1, a2, a3, w.x, w.y);
    }
}

template<int NS>
__device__ __forceinline__ void run_kloopv(const char* aBase, const char* smB,
        int kc_lo, int kc_hi, int rowA0, int tid4, int lane, float (&acc)[NS][4]) {
    const int EB = (NS == 9) ? 2304 : 2560;
    const char* wk = smB + kc_lo * 2 * EB;
    uint4 cur[2], nxt[2];
    ldA128(cur, aBase, rowA0, tid4, kc_lo, HPAD * 2);
#pragma unroll
    for (int p = 0; p < 2; ++p) nxt[p] = cur[p];
#pragma unroll 1
    for (int kc = kc_lo; kc < kc_hi; ++kc) {
        if (kc + 1 < kc_hi) ldA128(nxt, aBase, rowA0, tid4, kc + 1, HPAD * 2);
        slots_v<NS>(wk,      lane, cur, false, acc);
        slots_v<NS>(wk + EB, lane, cur, true,  acc);
        wk += 2 * EB;
#pragma unroll
        for (int p = 0; p < 2; ++p) cur[p] = nxt[p];
    }
}

template<int NS>
__device__ __forceinline__ void writePB(__half* PBh, int grp, const float (&acc)[NS][4],
                                        int rowA0, int tid4) {
#pragma unroll
    for (int s = 0; s < NS; ++s)
#pragma unroll
        for (int p = 0; p < 2; ++p) {
            int b = rowA0 + p * 8;
            __half2 v = __floats2half2_rn(acc[s][p * 2], acc[s][p * 2 + 1]);
            *(__half2*)(PBh + (grp * NS + s) * 512 + b * 8 + tid4 * 2) = v;
        }
}
template<int NS>
__device__ __forceinline__ void addPB(__half* PBh, int grp, float (&acc)[NS][4],
                                      int rowA0, int tid4) {
#pragma unroll
    for (int s = 0; s < NS; ++s)
#pragma unroll
        for (int p = 0; p < 2; ++p) {
            int b = rowA0 + p * 8;
            __half2 u = *(__half2*)(PBh + (grp * NS + s) * 512 + b * 8 + tid4 * 2);
            acc[s][p * 2]     += __low2float(u);
            acc[s][p * 2 + 1] += __high2float(u);
        }
}

// gather one gate pre-activation: sum of 4 fp16 partials
__device__ __forceinline__ float gatherPB(const __half* PBh, int s, int hidx) {
    float v = __half2float(PBh[(0 * 9 + s) * 512 + hidx]);
    v += __half2float(PBh[(1 * 9 + s) * 512 + hidx]);
    v += __half2float(PBh[(2 * 9 + s) * 512 + hidx]);
    v += __half2float(PBh[(3 * 9 + s) * 512 + hidx]);
    return v;
}

// ---------------- persistent kernel (512 threads) ----------------
__global__ void __launch_bounds__(NTH, 1) gru_main(
    const float* __restrict__ b_ih0, const float* __restrict__ b_hh0,
    const float* __restrict__ b_ih1, const float* __restrict__ b_hh1,
    float* __restrict__ out)
{
    extern __shared__ char sm[];
    const int cta  = blockIdx.x;
    const int tid  = threadIdx.x;
    const int wid  = tid >> 5;
    const int lane = tid & 31;
    const int mw   = wid >> 2;
    const int kw   = wid & 3;
    const int g    = lane >> 2;
    const int tid4 = lane & 3;
    const int cls  = (cta < 50) ? 0 : (cta < 95) ? 1 : 2;
    const int nbig = (cls == 1) ? 10 : 9;

    const int kc_lo = (kw == 0) ? 0 : (kw == 1) ? 9 : (kw == 2) ? 19 : 29;
    const int kc_hi = (kw == 0) ? 9 : (kw == 1) ? 19 : (kw == 2) ? 29 : 38;
    const int rowA0 = mw * 16 + g;

    // smem layout:
    // cls0: PB@179712 (4*9*1024=36864) -> AI fp32@216576 (6144) -> hbuf@222720
    // cls1: PB@194560 (2*10*1024=20480) (R12 tree)
    // cls2: PB@175104 (36864) -> hbuf@211968
    const int PB_off = (cls == 0) ? 179712 : (cls == 1) ? 194560 : 175104;
    __half* PBh = (__half*)(sm + PB_off);
    float*  AI  = (float*)(sm + 216576);
    __half* hbuf = (__half*)(sm + ((cls == 0) ? 222720 : 211968));

    // combine mapping: cl = tid&7, b = tid>>3, j = q*8+cl (q=0..2)
    const int ccl = tid & 7;
    const int cb  = tid >> 3;

    // ---- load resident weights ----
    {
        const uint2* wsrc = g_Wpk + (size_t)cta * WSTRIDE;
        int n16 = (cls == 1) ? 12160 : 10944;
        for (int i = tid; i < n16; i += NTH)
            cpa16(sm + i * 16, wsrc + i * 2);
        if (cls == 0) {
            const uint2* xs = g_Wxp + cta * 576;
            for (int i = tid; i < 288; i += NTH)
                cpa16(sm + SM_XW + i * 16, xs + i * 2);
        }
        cp_commit();
        cp_wait<0>();
        __syncthreads();
    }

    // ---- combine-side setup (3 elements per thread, new mapping) ----
    const int jbase = (cls == 0) ? cta * 24 : (cls == 2) ? (cta - 95) * 24 : 0;
    float bias[3][4];
    float hprev[3];
    if (cls != 1) {
        const float* bi = (cls == 0) ? b_ih0 : b_ih1;
        const float* bh = (cls == 0) ? b_hh0 : b_hh1;
#pragma unroll
        for (int q = 0; q < 3; ++q) {
            int jg = jbase + q * 8 + ccl;
            bias[q][0] = __ldg(bi + jg) + __ldg(bh + jg);
            bias[q][1] = __ldg(bi + 1200 + jg) + __ldg(bh + 1200 + jg);
            bias[q][2] = __ldg(bi + 2400 + jg);
            bias[q][3] = __ldg(bh + 2400 + jg);
            hprev[q] = 0.f;
        }
    }

    for (int r = 0; r < ROUNDS; ++r) {
        const bool act = (cls == 0) ? (r < TS)
                        : (cls == 1) ? (r >= 1 && r <= TS)
                                     : (r >= 2);
        if (act) {
            if (cls == 1) {
                // ---------------- I1 (R12 2-phase tree, unchanged) ----------------
                float acc[10][4];
#pragma unroll
                for (int s = 0; s < 10; ++s)
#pragma unroll
                    for (int c = 0; c < 4; ++c) acc[s][c] = 0.f;

                const char* aBase = (const char*)g_h0h[(r + 1) & 1];
                run_kloopv<10>(aBase, sm, kc_lo, kc_hi, rowA0, tid4, lane, acc);

                if (kw == 1) writePB<10>(PBh, 0, acc, rowA0, tid4);
                if (kw == 3) writePB<10>(PBh, 1, acc, rowA0, tid4);
                __syncthreads();
                if (kw == 0) addPB<10>(PBh, 0, acc, rowA0, tid4);
                if (kw == 2) { addPB<10>(PBh, 1, acc, rowA0, tid4);
                               writePB<10>(PBh, 1, acc, rowA0, tid4); }
                __syncthreads();
                if (kw == 0) {
                    addPB<10>(PBh, 1, acc, rowA0, tid4);
                    float* gw = g_gi1[(r - 1) & 1];
#pragma unroll
                    for (int s = 0; s < 10; ++s)
#pragma unroll
                        for (int p = 0; p < 2; ++p) {
                            int b = rowA0 + p * 8;
                            int gr = ((cta - 50) * 10 + s) * 8 + tid4 * 2;
                            __stcg(gw + (size_t)gr * BT + b, acc[s][p * 2]);
                            __stcg(gw + (size_t)(gr + 1) * BT + b, acc[s][p * 2 + 1]);
                        }
                }
            } else {
                // ---------------- L0 / H1 (flat reduction) ----------------
                float acc[9][4];
#pragma unroll
                for (int s = 0; s < 9; ++s)
#pragma unroll
                    for (int c = 0; c < 4; ++c) acc[s][c] = 0.f;

                const char* aBase = (cls == 2) ? (const char*)g_h1h[(r + 1) & 1]
                                               : (const char*)g_h0h[(r + 1) & 1];

                float accIN[3][4];
                if (cls == 0 && kw == 3) {
#pragma unroll
                    for (int s = 0; s < 3; ++s)
#pragma unroll
                        for (int c = 0; c < 4; ++c) accIN[s][c] = 0.f;
                    const char* xb = (const char*)g_x16 + (size_t)r * 4096;
                    uint4 xa[2];
                    ldA128(xa, xb, rowA0, tid4, 0, 64);
#pragma unroll
                    for (int s = 0; s < 9; ++s) {
                        uint2 w0 = *(const uint2*)(sm + SM_XW + (s * 2) * 256 + lane * 8);
                        uint2 w1 = *(const uint2*)(sm + SM_XW + (s * 2 + 1) * 256 + lane * 8);
                        float* tgt = (s < 6) ? acc[s] : accIN[s - 6];
                        mma_16816(tgt, xa[0].x, xa[1].x, xa[0].y, xa[1].y, w0.x, w0.y);
                        mma_16816(tgt, xa[0].z, xa[1].z, xa[0].w, xa[1].w, w1.x, w1.y);
                    }
                }

                run_kloopv<9>(aBase, sm, kc_lo, kc_hi, rowA0, tid4, lane, acc);

                float giPre[3][3];
                if (cls == 2) {
                    const float* gi = g_gi1[r & 1];
#pragma unroll
                    for (int q = 0; q < 3; ++q) {
                        int jg = jbase + q * 8 + ccl;
                        giPre[q][0] = __ldcg(gi + (size_t)jg * BT + cb);
                        giPre[q][1] = __ldcg(gi + (size_t)(1200 + jg) * BT + cb);
                        giPre[q][2] = __ldcg(gi + (size_t)(2400 + jg) * BT + cb);
                    }
                }

                // all four groups publish partials; kw3 also publishes i_n (fp32)
                writePB<9>(PBh, kw, acc, rowA0, tid4);
                if (cls == 0 && kw == 3) {
#pragma unroll
                    for (int s = 0; s < 3; ++s)
#pragma unroll
                        for (int p = 0; p < 2; ++p) {
                            int b = rowA0 + p * 8;
                            float* pp = AI + s * 512 + b * 8 + tid4 * 2;
                            pp[0] = accIN[s][p * 2];
                            pp[1] = accIN[s][p * 2 + 1];
                        }
                }
                __syncthreads();

                // ---- direct-gather combine (3 elements/thread, conflict-free) ----
                if (cls == 0) {
#pragma unroll
                    for (int q = 0; q < 3; ++q) {
                        int hidx = cb * 8 + ccl;
                        float pR  = gatherPB(PBh, q,     hidx);
                        float pZ  = gatherPB(PBh, 3 + q, hidx);
                        float pHN = gatherPB(PBh, 6 + q, hidx);
                        float pIN = AI[q * 512 + hidx];
                        float vr = sigf(pR + bias[q][0]);
                        float vz = sigf(pZ + bias[q][1]);
                        float vn = tanhf_fast(pIN + bias[q][2] + vr * (pHN + bias[q][3]));
                        float h = vn + vz * (hprev[q] - vn);
                        hprev[q] = h;
                        int j = q * 8 + ccl;
                        hbuf[cb * 26 + j] = __float2half_rn(h);
                        if (r == TS - 1) out[(size_t)cb * HIDN + jbase + j] = h;
                    }
                } else {
#pragma unroll
                    for (int q = 0; q < 3; ++q) {
                        int hidx = cb * 8 + ccl;
                        float pR  = gatherPB(PBh, q,     hidx);
                        float pZ  = gatherPB(PBh, 3 + q, hidx);
                        float pHN = gatherPB(PBh, 6 + q, hidx);
                        float vr = sigf(giPre[q][0] + pR + bias[q][0]);
                        float vz = sigf(giPre[q][1] + pZ + bias[q][1]);
                        float vn = tanhf_fast(giPre[q][2] + bias[q][2] + vr * (pHN + bias[q][3]));
                        float h = vn + vz * (hprev[q] - vn);
                        hprev[q] = h;
                        int j = q * 8 + ccl;
                        hbuf[cb * 26 + j] = __float2half_rn(h);
                        if (r == TS + 1) out[76800 + (size_t)cb * HIDN + jbase + j] = h;
                    }
                }
                __syncthreads();
                {
                    __half* dstH = (cls == 0) ? g_h0h[r & 1] : g_h1h[r & 1];
                    const unsigned* hb32 = (const unsigned*)hbuf;
#pragma unroll
                    for (int k = 0; k < 2; ++k) {
                        int idx = tid + k * NTH;
                        if (idx < 768) {
                            int row = idx / 12, c = idx % 12;
                            unsigned v = hb32[row * 13 + c];
                            asm volatile("st.global.cg.u32 [%0], %1;"
                                         :: "l"(dstH + (size_t)row * HPAD + jbase + c * 2),
                                            "r"(v) : "memory");
                        }
                    }
                }
            }
        }

        // ---- grid barrier (R12 exact) ----
        __threadfence();
        __syncthreads();
        if (tid == 0) {
            unsigned a = atomicAdd(&g_arr, 1u);
            if (a == NCTA - 1) {
                g_arr = 0u;
                __threadfence();
                atomicExch(&g_epoch, (unsigned)(r + 1));
            } else {
                unsigned e;
                int slp = 16;
                while (true) {
                    asm volatile("ld.global.cg.u32 %0,[%1];" : "=r"(e) : "l"(&g_epoch));
                    if (e >= (unsigned)(r + 1)) break;
                    __nanosleep(slp);
                    if (slp < 128) slp += slp;
                }
                __threadfence();
            }
        }
        __syncthreads();
    }
}

// ---------------- launch ----------------
extern "C" void kernel_launch(void* const* d_in, const int* in_sizes, int n_in,
                              void* d_out, int out_size) {
    const float* x     = (const float*)d_in[0];
    const float* W_ih0 = (const float*)d_in[1];
    const float* W_hh0 = (const float*)d_in[2];
    const float* b_ih0 = (const float*)d_in[3];
    const float* b_hh0 = (const float*)d_in[4];
    const float* W_ih1 = (const float*)d_in[5];
    const float* W_hh1 = (const float*)d_in[6];
    const float* b_ih1 = (const float*)d_in[7];
    const float* b_hh1 = (const float*)d_in[8];
    float* out = (float*)d_out;

    cudaFuncSetAttribute(gru_main,
                         cudaFuncAttributeMaxDynamicSharedMemorySize, SMEM_TOTAL);

    prep_all<<<18592, 256>>>(x, W_ih0, W_hh0, W_ih1, W_hh1);
    gru_main<<<NCTA, NTH, SMEM_TOTAL>>>(b_ih0, b_hh0, b_ih1, b_hh1, out);
}